// round 1
// baseline (speedup 1.0000x reference)
#include <cuda_runtime.h>
#include <cstdint>
#include <cstddef>

#define T_STEPS 512
#define BATCH   64
#define HID     1024
#define G4      4096
#define M1      (T_STEPS * BATCH)   // 32768
#define NCTA    128

// ---------------- device scratch (no allocs allowed) ----------------
__device__ float    g_xpre[(size_t)M1 * G4];      // 512 MB: [T*B, 4H]
__device__ float    g_hbuf[2][BATCH * HID];       // double-buffered h
__device__ unsigned g_bar;

__global__ void reset_bar_k() { g_bar = 0u; }

// ---------------- phase 1: x_pre = input @ W_ih^T + b_ih + b_hh ----------------
// A: [M1, 1024] row-major (K contiguous), W: [4096, 1024] row-major (K contiguous)
// C[m][n] = sum_k A[m][k] * W[n][k]   -> classic 128x128x16 SGEMM
__global__ __launch_bounds__(256) void sgemm_xpre_k(
    const float* __restrict__ A, const float* __restrict__ W,
    const float* __restrict__ bih, const float* __restrict__ bhh) {
    __shared__ float As[16][132];
    __shared__ float Bs[16][132];

    const int tid = threadIdx.x;
    const int m0 = blockIdx.y * 128;
    const int n0 = blockIdx.x * 128;
    const int tx = tid & 15;        // 0..15 -> n
    const int ty = tid >> 4;        // 0..15 -> m
    const int lr = tid >> 2;        // 0..63 loader row
    const int lc = (tid & 3) << 2;  // 0,4,8,12 loader k offset

    float acc[8][8];
#pragma unroll
    for (int i = 0; i < 8; i++)
#pragma unroll
        for (int j = 0; j < 8; j++) acc[i][j] = 0.0f;

    const float* Arow0 = A + (size_t)(m0 + lr) * 1024 + lc;
    const float* Arow1 = Arow0 + (size_t)64 * 1024;
    const float* Wrow0 = W + (size_t)(n0 + lr) * 1024 + lc;
    const float* Wrow1 = Wrow0 + (size_t)64 * 1024;

    for (int k0 = 0; k0 < 1024; k0 += 16) {
        float4 a0 = *(const float4*)(Arow0 + k0);
        float4 a1 = *(const float4*)(Arow1 + k0);
        float4 w0 = *(const float4*)(Wrow0 + k0);
        float4 w1 = *(const float4*)(Wrow1 + k0);
        __syncthreads();
        As[lc + 0][lr] = a0.x; As[lc + 1][lr] = a0.y;
        As[lc + 2][lr] = a0.z; As[lc + 3][lr] = a0.w;
        As[lc + 0][lr + 64] = a1.x; As[lc + 1][lr + 64] = a1.y;
        As[lc + 2][lr + 64] = a1.z; As[lc + 3][lr + 64] = a1.w;
        Bs[lc + 0][lr] = w0.x; Bs[lc + 1][lr] = w0.y;
        Bs[lc + 2][lr] = w0.z; Bs[lc + 3][lr] = w0.w;
        Bs[lc + 0][lr + 64] = w1.x; Bs[lc + 1][lr + 64] = w1.y;
        Bs[lc + 2][lr + 64] = w1.z; Bs[lc + 3][lr + 64] = w1.w;
        __syncthreads();
#pragma unroll
        for (int kk = 0; kk < 16; kk++) {
            float ar[8], br[8];
            *(float4*)&ar[0] = *(const float4*)&As[kk][ty * 8];
            *(float4*)&ar[4] = *(const float4*)&As[kk][ty * 8 + 4];
            *(float4*)&br[0] = *(const float4*)&Bs[kk][tx * 8];
            *(float4*)&br[4] = *(const float4*)&Bs[kk][tx * 8 + 4];
#pragma unroll
            for (int i = 0; i < 8; i++)
#pragma unroll
                for (int j = 0; j < 8; j++)
                    acc[i][j] = fmaf(ar[i], br[j], acc[i][j]);
        }
    }

#pragma unroll
    for (int j = 0; j < 8; j++) {
        const int n = n0 + tx * 8 + j;
        const float bias = bih[n] + bhh[n];
#pragma unroll
        for (int i = 0; i < 8; i++) {
            const int m = m0 + ty * 8 + i;
            g_xpre[(size_t)m * G4 + n] = acc[i][j] + bias;
        }
    }
}

// ---------------- grid-wide barrier (co-resident persistent kernel) ----------------
__device__ __forceinline__ void gbar(unsigned target) {
    __syncthreads();
    if (threadIdx.x == 0) {
        __threadfence();
        atomicAdd(&g_bar, 1u);
        while (*((volatile unsigned*)&g_bar) < target) { __nanosleep(64); }
    }
    __syncthreads();
}

// ---------------- phase 2: persistent recurrence ----------------
// 128 CTAs. CTA owns h-columns [cta*8, cta*8+8) for all 4 gates -> 32 gate cols.
// Per step: pre[64][32] = h @ W_hh_cols + x_pre, then CTA-local gate math.
__global__ __launch_bounds__(256) void lstm_rec_k(
    const float* __restrict__ Whh, const float* __restrict__ h0,
    const float* __restrict__ c0, float* __restrict__ out) {
    __shared__ float h_s[64][36];     // [b][k-chunk], padded, fp32
    __shared__ float w_s[32][33];     // [kk][col]
    __shared__ float pre_s[64][32];   // [b][gate-col]

    const int cta = blockIdx.x;
    const int tid = threadIdx.x;
    const int col = tid & 31;         // gate-column within CTA (0..31)
    const int bgrp = tid >> 5;        // batch-row group (0..7), 8 rows each
    const int hcbase = cta * 8;
    const int gcol = (col >> 3) * HID + hcbase + (col & 7);

    // W loader: thread -> (wcol 0..31, wkq 0..7); row pointer fixed for kernel lifetime
    const int wcol = tid >> 3;
    const int wkq  = tid & 7;
    const int wg = wcol >> 3, whc = wcol & 7;
    const float* wptr = Whh + (size_t)(wg * HID + hcbase + whc) * HID + wkq * 4;

    // h loader: thread -> (hb 0..31, hkq 0..7); also handles hb+32
    const int hb  = tid >> 3;
    const int hkq = tid & 7;

    // update cells: thread owns (ub, uhc) and (ub+32, uhc)
    const int ub  = tid >> 3;
    const int uhc = tid & 7;
    const int uidx0 = ub * HID + hcbase + uhc;
    const int uidx1 = uidx0 + 32 * HID;

    float creg0 = c0[uidx0];
    float creg1 = c0[uidx1];
    g_hbuf[0][uidx0] = h0[uidx0];
    g_hbuf[0][uidx1] = h0[uidx1];
    float hlast0 = 0.0f, hlast1 = 0.0f;

    unsigned target = NCTA;
    gbar(target);

    for (int t = 0; t < T_STEPS; t++) {
        const float* hin  = g_hbuf[t & 1];
        float*       hout = g_hbuf[(t + 1) & 1];

        float acc[8];
#pragma unroll
        for (int i = 0; i < 8; i++) acc[i] = 0.0f;

        const float* hld0 = hin + hb * HID + hkq * 4;
        const float* hld1 = hld0 + 32 * HID;

        for (int k0 = 0; k0 < HID; k0 += 32) {
            const float4 hv0 = __ldcg((const float4*)(hld0 + k0));   // L2, never-stale
            const float4 hv1 = __ldcg((const float4*)(hld1 + k0));
            const float4 wv  = *(const float4*)(wptr + k0);          // L1-resident across steps
            __syncthreads();   // previous chunk's compute done before overwrite
            *(float4*)&h_s[hb][hkq * 4]      = hv0;
            *(float4*)&h_s[hb + 32][hkq * 4] = hv1;
            w_s[wkq * 4 + 0][wcol] = wv.x;
            w_s[wkq * 4 + 1][wcol] = wv.y;
            w_s[wkq * 4 + 2][wcol] = wv.z;
            w_s[wkq * 4 + 3][wcol] = wv.w;
            __syncthreads();
#pragma unroll
            for (int kk = 0; kk < 32; kk += 4) {
                const float w0 = w_s[kk + 0][col];
                const float w1 = w_s[kk + 1][col];
                const float w2 = w_s[kk + 2][col];
                const float w3 = w_s[kk + 3][col];
#pragma unroll
                for (int b8 = 0; b8 < 8; b8++) {
                    const float4 hv = *(const float4*)&h_s[bgrp * 8 + b8][kk];  // broadcast
                    float a = acc[b8];
                    a = fmaf(hv.x, w0, a);
                    a = fmaf(hv.y, w1, a);
                    a = fmaf(hv.z, w2, a);
                    a = fmaf(hv.w, w3, a);
                    acc[b8] = a;
                }
            }
        }

        // add x_pre, publish pre to smem
        const float* xp = g_xpre + (size_t)t * BATCH * G4;
#pragma unroll
        for (int b8 = 0; b8 < 8; b8++) {
            const int b = bgrp * 8 + b8;
            pre_s[b][col] = acc[b8] + xp[b * G4 + gcol];
        }
        __syncthreads();

        // gate math for the 2 owned cells
        {
            const float pi = pre_s[ub][uhc];
            const float pf = pre_s[ub][8 + uhc];
            const float po = pre_s[ub][16 + uhc];
            const float pg = pre_s[ub][24 + uhc];
            const float ig = 1.0f / (1.0f + __expf(-pi));
            const float fg = 1.0f / (1.0f + __expf(-pf));
            const float og = 1.0f / (1.0f + __expf(-po));
            creg0 = fg * creg0 + ig * tanhf(pg);
            hlast0 = og * tanhf(creg0);
        }
        {
            const int b2 = ub + 32;
            const float pi = pre_s[b2][uhc];
            const float pf = pre_s[b2][8 + uhc];
            const float po = pre_s[b2][16 + uhc];
            const float pg = pre_s[b2][24 + uhc];
            const float ig = 1.0f / (1.0f + __expf(-pi));
            const float fg = 1.0f / (1.0f + __expf(-pf));
            const float og = 1.0f / (1.0f + __expf(-po));
            creg1 = fg * creg1 + ig * tanhf(pg);
            hlast1 = og * tanhf(creg1);
        }
        hout[uidx0] = hlast0;
        hout[uidx1] = hlast1;
        float* orow = out + (size_t)t * (BATCH * HID);
        orow[uidx0] = hlast0;
        orow[uidx1] = hlast1;

        target += NCTA;
        gbar(target);
    }

    // finals: out = [output | h_f | c_f]
    float* hf = out + (size_t)T_STEPS * BATCH * HID;
    float* cf = hf + BATCH * HID;
    hf[uidx0] = hlast0;
    hf[uidx1] = hlast1;
    cf[uidx0] = creg0;
    cf[uidx1] = creg1;
}

// ---------------- launch ----------------
extern "C" void kernel_launch(void* const* d_in, const int* in_sizes, int n_in,
                              void* d_out, int out_size) {
    const float* input = (const float*)d_in[0];   // [T, B, I]
    const float* h0    = (const float*)d_in[1];   // [1, B, H]
    const float* c0    = (const float*)d_in[2];   // [1, B, H]
    const float* W_ih  = (const float*)d_in[3];   // [4H, I]
    const float* b_ih  = (const float*)d_in[4];   // [4H]
    const float* W_hh  = (const float*)d_in[5];   // [4H, H]
    const float* b_hh  = (const float*)d_in[6];   // [4H]
    float* out = (float*)d_out;

    reset_bar_k<<<1, 1>>>();
    dim3 g1(G4 / 128, M1 / 128);   // (32, 256)
    sgemm_xpre_k<<<g1, 256>>>(input, W_ih, b_ih, b_hh);
    lstm_rec_k<<<NCTA, 256>>>(W_hh, h0, c0, out);
}

// round 2
// speedup vs baseline: 1.7876x; 1.7876x over previous
#include <cuda_runtime.h>
#include <cstdint>
#include <cstddef>

#define T_STEPS 512
#define BATCH   64
#define HID     1024
#define G4      4096
#define M1      (T_STEPS * BATCH)   // 32768
#define NCTA    128

// ---------------- device scratch (no allocs allowed) ----------------
__device__ float    g_xpre[(size_t)M1 * G4];      // 512 MB: [T*B, 4H]
__device__ float    g_hbuf[2][BATCH * HID];       // double-buffered h, A-fragment-major layout
__device__ unsigned g_bar;

__global__ void reset_bar_k() { g_bar = 0u; }

// ---------------- helpers ----------------
__device__ __forceinline__ uint32_t f2tf32(float x) {
    uint32_t r;
    asm("cvt.rna.tf32.f32 %0, %1;" : "=r"(r) : "f"(x));
    return r;
}

__device__ __forceinline__ void mma_tf32(float* c, const uint32_t* a, const uint32_t* b) {
    asm volatile(
        "mma.sync.aligned.m16n8k8.row.col.f32.tf32.tf32.f32 "
        "{%0,%1,%2,%3}, {%4,%5,%6,%7}, {%8,%9}, {%0,%1,%2,%3};"
        : "+f"(c[0]), "+f"(c[1]), "+f"(c[2]), "+f"(c[3])
        : "r"(a[0]), "r"(a[1]), "r"(a[2]), "r"(a[3]), "r"(b[0]), "r"(b[1]));
}

// ---------------- phase 1: x_pre = input @ W_ih^T + b_ih + b_hh (tf32 mma) ----------------
// A: [M1,1024] row-major (k contig). W: [4096,1024] row-major (k contig) == col-major K x N.
// CTA tile 128x128, 8 warps in 4(M) x 2(N), warp tile 32x64 = 2 m16 x 8 n8. K-chunk 16.
__global__ __launch_bounds__(256) void gemm1_k(
    const float* __restrict__ A, const float* __restrict__ W,
    const float* __restrict__ bih, const float* __restrict__ bhh) {
    __shared__ uint32_t As[128][20];   // ld=20: fragment reads are bank-conflict-free
    __shared__ uint32_t Bs[128][20];

    const int tid   = threadIdx.x;
    const int lane  = tid & 31;
    const int wid   = tid >> 5;
    const int warpM = wid & 3;
    const int warpN = wid >> 2;
    const int m0 = blockIdx.y * 128;
    const int n0 = blockIdx.x * 128;

    // loader: 512 float4 per array per chunk; thread -> (row tid>>2 & +64, f4col tid&3)
    const int r1 = tid >> 2;
    const int r2 = r1 + 64;
    const int c4 = (tid & 3) * 4;

    float acc[2][8][4];
#pragma unroll
    for (int mt = 0; mt < 2; mt++)
#pragma unroll
        for (int nt = 0; nt < 8; nt++)
#pragma unroll
            for (int r = 0; r < 4; r++) acc[mt][nt][r] = 0.0f;

    const float* Ap1 = A + (size_t)(m0 + r1) * 1024 + c4;
    const float* Ap2 = A + (size_t)(m0 + r2) * 1024 + c4;
    const float* Wp1 = W + (size_t)(n0 + r1) * 1024 + c4;
    const float* Wp2 = W + (size_t)(n0 + r2) * 1024 + c4;

    const int g  = lane >> 2;   // group id
    const int tg = lane & 3;    // thread-in-group

    for (int k0 = 0; k0 < 1024; k0 += 16) {
        const float4 a1 = *(const float4*)(Ap1 + k0);
        const float4 a2 = *(const float4*)(Ap2 + k0);
        const float4 b1 = *(const float4*)(Wp1 + k0);
        const float4 b2 = *(const float4*)(Wp2 + k0);
        __syncthreads();
        {
            uint4 u;
            u.x = f2tf32(a1.x); u.y = f2tf32(a1.y); u.z = f2tf32(a1.z); u.w = f2tf32(a1.w);
            *(uint4*)&As[r1][c4] = u;
            u.x = f2tf32(a2.x); u.y = f2tf32(a2.y); u.z = f2tf32(a2.z); u.w = f2tf32(a2.w);
            *(uint4*)&As[r2][c4] = u;
            u.x = f2tf32(b1.x); u.y = f2tf32(b1.y); u.z = f2tf32(b1.z); u.w = f2tf32(b1.w);
            *(uint4*)&Bs[r1][c4] = u;
            u.x = f2tf32(b2.x); u.y = f2tf32(b2.y); u.z = f2tf32(b2.z); u.w = f2tf32(b2.w);
            *(uint4*)&Bs[r2][c4] = u;
        }
        __syncthreads();

#pragma unroll
        for (int ksl = 0; ksl < 2; ksl++) {
            const int kb = ksl * 8;
            uint32_t af[2][4];
#pragma unroll
            for (int mt = 0; mt < 2; mt++) {
                const int mb = warpM * 32 + mt * 16;
                af[mt][0] = As[mb + g][kb + tg];
                af[mt][1] = As[mb + 8 + g][kb + tg];
                af[mt][2] = As[mb + g][kb + 4 + tg];
                af[mt][3] = As[mb + 8 + g][kb + 4 + tg];
            }
#pragma unroll
            for (int nt = 0; nt < 8; nt++) {
                const int nb = warpN * 64 + nt * 8;
                uint32_t bf[2];
                bf[0] = Bs[nb + g][kb + tg];
                bf[1] = Bs[nb + g][kb + 4 + tg];
                mma_tf32(acc[0][nt], af[0], bf);
                mma_tf32(acc[1][nt], af[1], bf);
            }
        }
    }

    // epilogue: add bias, store fp32 to g_xpre
#pragma unroll
    for (int nt = 0; nt < 8; nt++) {
        const int col = n0 + warpN * 64 + nt * 8 + 2 * tg;
        const float bias0 = bih[col] + bhh[col];
        const float bias1 = bih[col + 1] + bhh[col + 1];
#pragma unroll
        for (int mt = 0; mt < 2; mt++) {
            const int row = m0 + warpM * 32 + mt * 16 + g;
            float2 v0; v0.x = acc[mt][nt][0] + bias0; v0.y = acc[mt][nt][1] + bias1;
            *(float2*)&g_xpre[(size_t)row * G4 + col] = v0;
            float2 v1; v1.x = acc[mt][nt][2] + bias0; v1.y = acc[mt][nt][3] + bias1;
            *(float2*)&g_xpre[(size_t)(row + 8) * G4 + col] = v1;
        }
    }
}

// ---------------- grid-wide barrier ----------------
__device__ __forceinline__ void gbar(unsigned target) {
    __syncthreads();
    if (threadIdx.x == 0) {
        __threadfence();
        atomicAdd(&g_bar, 1u);
        while (*((volatile unsigned*)&g_bar) < target) { __nanosleep(64); }
    }
    __syncthreads();
}

// ---------------- phase 2: persistent recurrence (tf32 mma) ----------------
// 128 CTAs x 128 threads (4 warps). CTA owns 32 gate-cols: {g*1024 + cta*8 + u}.
// W_hh slice lives in smem pre-arranged in B-fragment order (LDS.64 per mma).
// h lives in global in A-fragment order: element (b,k) at
//   ((mt*128 + ks)*32 + lane)*4 + j,  mt=b>>4, ks=k>>3, lane=(b&7)*4+(k&3), j=((k>>2)&1)*2+((b>>3)&1)
// so warp mt feeds mma with one coalesced LDG.128 per k-step.
__global__ __launch_bounds__(128) void lstm_rec_k(
    const float* __restrict__ Whh, const float* __restrict__ h0,
    const float* __restrict__ c0, float* __restrict__ out) {
    extern __shared__ uint32_t smem[];
    uint32_t* W_s  = smem;                         // 4*128*32*2 = 32768 words (128 KB)
    float*    pre_s = (float*)(smem + 32768);      // [64][33]

    const int tid    = threadIdx.x;
    const int lane   = tid & 31;
    const int w      = tid >> 5;                   // warp id == mtile
    const int cta    = blockIdx.x;
    const int hcbase = cta * 8;

    // ---- fill W fragments (one-time) ----
    for (int idx = tid; idx < 16384; idx += 128) {
        const int li = idx & 31;
        const int ks = (idx >> 5) & 127;
        const int n  = idx >> 12;                  // gate / ntile
        const size_t row = (size_t)(n * HID + hcbase + (li >> 2)) * HID;
        const int k = ks * 8 + (li & 3);
        W_s[idx * 2]     = f2tf32(__ldg(&Whh[row + k]));
        W_s[idx * 2 + 1] = f2tf32(__ldg(&Whh[row + k + 4]));
    }

    // ---- cell ownership: thread owns hcol u, batches {bq, bq+16, bq+32, bq+48} ----
    const int u  = tid & 7;
    const int bq = tid >> 3;                       // 0..15
    const int lane_f = (bq & 7) * 4 + (u & 3);
    const int jreg   = (u >> 2) * 2 + (bq >> 3);

    float c_r[4], h_r[4];
#pragma unroll
    for (int j = 0; j < 4; j++) {
        const int b   = bq + 16 * j;
        const int idx = b * HID + hcbase + u;
        c_r[j] = c0[idx];
        const float h = h0[idx];
        h_r[j] = h;
        g_hbuf[0][((size_t)(j * 128 + cta) * 32 + lane_f) * 4 + jreg] =
            __uint_as_float(f2tf32(h));
    }

    unsigned target = NCTA;
    gbar(target);

    for (int t = 0; t < T_STEPS; t++) {
        const float* hin  = g_hbuf[t & 1];
        float*       hout = g_hbuf[(t + 1) & 1];

        float acc[4][4];
#pragma unroll
        for (int n = 0; n < 4; n++)
#pragma unroll
            for (int r = 0; r < 4; r++) acc[n][r] = 0.0f;

        const uint4* Af = (const uint4*)hin + (size_t)(w * 128) * 32 + lane;

        uint4 ab[2][8];
#pragma unroll
        for (int i = 0; i < 8; i++) ab[0][i] = __ldcg(Af + i * 32);

#pragma unroll
        for (int kc = 0; kc < 16; kc++) {
            const int cur = kc & 1;
            if (kc < 15) {
#pragma unroll
                for (int i = 0; i < 8; i++)
                    ab[cur ^ 1][i] = __ldcg(Af + ((kc + 1) * 8 + i) * 32);
            }
#pragma unroll
            for (int i = 0; i < 8; i++) {
                const int ks = kc * 8 + i;
#pragma unroll
                for (int n = 0; n < 4; n++) {
                    const uint2 bv = *(const uint2*)&W_s[((n * 128 + ks) * 32 + lane) * 2];
                    mma_tf32(acc[n], (const uint32_t*)&ab[cur][i], (const uint32_t*)&bv);
                }
            }
        }

        // publish pre to smem
        const int rg = lane >> 2;
        const int cg = 2 * (lane & 3);
#pragma unroll
        for (int n = 0; n < 4; n++) {
            const int colb = n * 8 + cg;
            const int rb   = w * 16 + rg;
            pre_s[rb * 33 + colb]           = acc[n][0];
            pre_s[rb * 33 + colb + 1]       = acc[n][1];
            pre_s[(rb + 8) * 33 + colb]     = acc[n][2];
            pre_s[(rb + 8) * 33 + colb + 1] = acc[n][3];
        }
        __syncthreads();

        // gate math + h/c update + stores
        const float* xp   = g_xpre + (size_t)t * BATCH * G4;
        float*       orow = out + (size_t)t * BATCH * HID;
#pragma unroll
        for (int j = 0; j < 4; j++) {
            const int b = bq + 16 * j;
            const float* pb = &pre_s[b * 33];
            const float* xb = xp + (size_t)b * G4 + hcbase + u;
            const float pi = pb[u]      + xb[0];
            const float pf = pb[8 + u]  + xb[HID];
            const float po = pb[16 + u] + xb[2 * HID];
            const float pg = pb[24 + u] + xb[3 * HID];
            const float ig = 1.0f / (1.0f + __expf(-pi));
            const float fg = 1.0f / (1.0f + __expf(-pf));
            const float og = 1.0f / (1.0f + __expf(-po));
            c_r[j] = fg * c_r[j] + ig * tanhf(pg);
            const float h = og * tanhf(c_r[j]);
            h_r[j] = h;
            orow[b * HID + hcbase + u] = h;
            hout[((size_t)(j * 128 + cta) * 32 + lane_f) * 4 + jreg] =
                __uint_as_float(f2tf32(h));
        }

        target += NCTA;
        gbar(target);
    }

    // finals: out = [output | h_f | c_f]
    float* hf = out + (size_t)T_STEPS * BATCH * HID;
    float* cf = hf + BATCH * HID;
#pragma unroll
    for (int j = 0; j < 4; j++) {
        const int b = bq + 16 * j;
        hf[b * HID + hcbase + u] = h_r[j];
        cf[b * HID + hcbase + u] = c_r[j];
    }
}

// ---------------- launch ----------------
extern "C" void kernel_launch(void* const* d_in, const int* in_sizes, int n_in,
                              void* d_out, int out_size) {
    const float* input = (const float*)d_in[0];   // [T, B, I]
    const float* h0    = (const float*)d_in[1];   // [1, B, H]
    const float* c0    = (const float*)d_in[2];   // [1, B, H]
    const float* W_ih  = (const float*)d_in[3];   // [4H, I]
    const float* b_ih  = (const float*)d_in[4];   // [4H]
    const float* W_hh  = (const float*)d_in[5];   // [4H, H]
    const float* b_hh  = (const float*)d_in[6];   // [4H]
    float* out = (float*)d_out;

    const int rec_smem = 32768 * 4 + 64 * 33 * 4;  // W_s + pre_s = 139968... (131072 + 8448)
    cudaFuncSetAttribute(lstm_rec_k, cudaFuncAttributeMaxDynamicSharedMemorySize, rec_smem);

    reset_bar_k<<<1, 1>>>();
    dim3 g1(G4 / 128, M1 / 128);   // (32, 256)
    gemm1_k<<<g1, 256>>>(input, W_ih, b_ih, b_hh);
    lstm_rec_k<<<NCTA, 128, rec_smem>>>(W_hh, h0, c0, out);
}

// round 4
// speedup vs baseline: 2.0668x; 1.1562x over previous
#include <cuda_runtime.h>
#include <cstdint>
#include <cstddef>

#define T_STEPS 512
#define BATCH   64
#define HID     1024
#define G4      4096
#define M1      (T_STEPS * BATCH)   // 32768
#define NCTA    128

// ---------------- device scratch (no allocs allowed) ----------------
__device__ float    g_xpre[(size_t)M1 * G4];      // 512 MB: [T*B, 4H]
__device__ float    g_hbuf[2][BATCH * HID];       // double-buffered h, A-fragment-major layout
__device__ unsigned g_cnt;                        // zero-init; self-resets each barrier
__device__ unsigned g_gen;                        // zero-init; monotonic across replays

// ---------------- helpers ----------------
__device__ __forceinline__ uint32_t f2tf32(float x) {
    uint32_t r;
    asm("cvt.rna.tf32.f32 %0, %1;" : "=r"(r) : "f"(x));
    return r;
}

__device__ __forceinline__ void mma_tf32(float* c, const uint32_t* a, const uint32_t* b) {
    asm volatile(
        "mma.sync.aligned.m16n8k8.row.col.f32.tf32.tf32.f32 "
        "{%0,%1,%2,%3}, {%4,%5,%6,%7}, {%8,%9}, {%0,%1,%2,%3};"
        : "+f"(c[0]), "+f"(c[1]), "+f"(c[2]), "+f"(c[3])
        : "r"(a[0]), "r"(a[1]), "r"(a[2]), "r"(a[3]), "r"(b[0]), "r"(b[1]));
}

// ---------------- phase 1: x_pre = input @ W_ih^T + b_ih + b_hh (tf32 mma) ----------------
// A: [M1,1024] row-major (k contig). W: [4096,1024] row-major (k contig).
// CTA tile 128x128, 8 warps in 4(M) x 2(N), warp tile 32x64. K-chunk 16, 2-stage pipeline.
__global__ __launch_bounds__(256) void gemm1_k(
    const float* __restrict__ A, const float* __restrict__ W,
    const float* __restrict__ bih, const float* __restrict__ bhh) {
    __shared__ uint32_t As[2][128][20];   // 10 KB per stage per array (40 KB total)
    __shared__ uint32_t Bs[2][128][20];

    const int tid   = threadIdx.x;
    const int lane  = tid & 31;
    const int wid   = tid >> 5;
    const int warpM = wid & 3;
    const int warpN = wid >> 2;
    const int m0 = blockIdx.y * 128;
    const int n0 = blockIdx.x * 128;

    const int r1 = tid >> 2;        // loader row (0..63), also +64
    const int r2 = r1 + 64;
    const int c4 = (tid & 3) * 4;   // k offset in chunk

    float acc[2][8][4];
#pragma unroll
    for (int mt = 0; mt < 2; mt++)
#pragma unroll
        for (int nt = 0; nt < 8; nt++)
#pragma unroll
            for (int r = 0; r < 4; r++) acc[mt][nt][r] = 0.0f;

    const float* Ap1 = A + (size_t)(m0 + r1) * 1024 + c4;
    const float* Ap2 = A + (size_t)(m0 + r2) * 1024 + c4;
    const float* Wp1 = W + (size_t)(n0 + r1) * 1024 + c4;
    const float* Wp2 = W + (size_t)(n0 + r2) * 1024 + c4;

    const int g  = lane >> 2;   // group id
    const int tg = lane & 3;    // thread-in-group

    float4 ra1, ra2, rb1, rb2;

    // prologue: load chunk 0 and stage it
    ra1 = *(const float4*)(Ap1);
    ra2 = *(const float4*)(Ap2);
    rb1 = *(const float4*)(Wp1);
    rb2 = *(const float4*)(Wp2);
    {
        uint4 u;
        u.x = f2tf32(ra1.x); u.y = f2tf32(ra1.y); u.z = f2tf32(ra1.z); u.w = f2tf32(ra1.w);
        *(uint4*)&As[0][r1][c4] = u;
        u.x = f2tf32(ra2.x); u.y = f2tf32(ra2.y); u.z = f2tf32(ra2.z); u.w = f2tf32(ra2.w);
        *(uint4*)&As[0][r2][c4] = u;
        u.x = f2tf32(rb1.x); u.y = f2tf32(rb1.y); u.z = f2tf32(rb1.z); u.w = f2tf32(rb1.w);
        *(uint4*)&Bs[0][r1][c4] = u;
        u.x = f2tf32(rb2.x); u.y = f2tf32(rb2.y); u.z = f2tf32(rb2.z); u.w = f2tf32(rb2.w);
        *(uint4*)&Bs[0][r2][c4] = u;
    }
    __syncthreads();

    for (int k = 0; k < 64; k++) {
        // issue loads for next chunk early: latency overlaps this chunk's mma
        if (k < 63) {
            const int off = (k + 1) * 16;
            ra1 = *(const float4*)(Ap1 + off);
            ra2 = *(const float4*)(Ap2 + off);
            rb1 = *(const float4*)(Wp1 + off);
            rb2 = *(const float4*)(Wp2 + off);
        }
        const int cur = k & 1;

#pragma unroll
        for (int ksl = 0; ksl < 2; ksl++) {
            const int kb = ksl * 8;
            uint32_t af[2][4];
#pragma unroll
            for (int mt = 0; mt < 2; mt++) {
                const int mb = warpM * 32 + mt * 16;
                af[mt][0] = As[cur][mb + g][kb + tg];
                af[mt][1] = As[cur][mb + 8 + g][kb + tg];
                af[mt][2] = As[cur][mb + g][kb + 4 + tg];
                af[mt][3] = As[cur][mb + 8 + g][kb + 4 + tg];
            }
#pragma unroll
            for (int nt = 0; nt < 8; nt++) {
                const int nb = warpN * 64 + nt * 8;
                uint32_t bf[2];
                bf[0] = Bs[cur][nb + g][kb + tg];
                bf[1] = Bs[cur][nb + g][kb + 4 + tg];
                mma_tf32(acc[0][nt], af[0], bf);
                mma_tf32(acc[1][nt], af[1], bf);
            }
        }
        __syncthreads();
        if (k < 63) {
            const int nxt = cur ^ 1;
            uint4 u;
            u.x = f2tf32(ra1.x); u.y = f2tf32(ra1.y); u.z = f2tf32(ra1.z); u.w = f2tf32(ra1.w);
            *(uint4*)&As[nxt][r1][c4] = u;
            u.x = f2tf32(ra2.x); u.y = f2tf32(ra2.y); u.z = f2tf32(ra2.z); u.w = f2tf32(ra2.w);
            *(uint4*)&As[nxt][r2][c4] = u;
            u.x = f2tf32(rb1.x); u.y = f2tf32(rb1.y); u.z = f2tf32(rb1.z); u.w = f2tf32(rb1.w);
            *(uint4*)&Bs[nxt][r1][c4] = u;
            u.x = f2tf32(rb2.x); u.y = f2tf32(rb2.y); u.z = f2tf32(rb2.z); u.w = f2tf32(rb2.w);
            *(uint4*)&Bs[nxt][r2][c4] = u;
            __syncthreads();
        }
    }

    // epilogue: add bias, store fp32 to g_xpre
#pragma unroll
    for (int nt = 0; nt < 8; nt++) {
        const int col = n0 + warpN * 64 + nt * 8 + 2 * tg;
        const float bias0 = bih[col] + bhh[col];
        const float bias1 = bih[col + 1] + bhh[col + 1];
#pragma unroll
        for (int mt = 0; mt < 2; mt++) {
            const int row = m0 + warpM * 32 + mt * 16 + g;
            float2 v0; v0.x = acc[mt][nt][0] + bias0; v0.y = acc[mt][nt][1] + bias1;
            *(float2*)&g_xpre[(size_t)row * G4 + col] = v0;
            float2 v1; v1.x = acc[mt][nt][2] + bias0; v1.y = acc[mt][nt][3] + bias1;
            *(float2*)&g_xpre[(size_t)(row + 8) * G4 + col] = v1;
        }
    }
}

// ---------------- grid-wide barrier: self-resetting, replay-safe ----------------
__device__ __forceinline__ void gbar() {
    __syncthreads();
    if (threadIdx.x == 0) {
        volatile unsigned* vgen = &g_gen;
        const unsigned gen0 = *vgen;      // stable: nobody can bump until we arrive
        __threadfence();                   // publish our h/c stores before arrival
        if (atomicAdd(&g_cnt, 1u) == NCTA - 1u) {
            g_cnt = 0u;                    // safe: all arrived, none can re-enter yet
            __threadfence();
            *vgen = gen0 + 1u;
        } else {
            while (*vgen == gen0) { __nanosleep(32); }
        }
    }
    __syncthreads();
}

// ---------------- phase 2: persistent recurrence (tf32 mma) ----------------
// 128 CTAs x 128 threads (4 warps). CTA owns 32 gate-cols: {g*1024 + cta*8 + u}.
// W_hh slice in smem in B-fragment order; h in global in A-fragment order.
__global__ __launch_bounds__(128) void lstm_rec_k(
    const float* __restrict__ Whh, const float* __restrict__ h0,
    const float* __restrict__ c0, float* __restrict__ out) {
    extern __shared__ uint32_t smem[];
    uint32_t* W_s  = smem;                         // 4*128*32*2 words (128 KB)
    float*    pre_s = (float*)(smem + 32768);      // [64][33]

    const int tid    = threadIdx.x;
    const int lane   = tid & 31;
    const int w      = tid >> 5;                   // warp id == mtile
    const int cta    = blockIdx.x;
    const int hcbase = cta * 8;

    // ---- fill W fragments (one-time) ----
    for (int idx = tid; idx < 16384; idx += 128) {
        const int li = idx & 31;
        const int ks = (idx >> 5) & 127;
        const int n  = idx >> 12;                  // gate / ntile
        const size_t row = (size_t)(n * HID + hcbase + (li >> 2)) * HID;
        const int k = ks * 8 + (li & 3);
        W_s[idx * 2]     = f2tf32(__ldg(&Whh[row + k]));
        W_s[idx * 2 + 1] = f2tf32(__ldg(&Whh[row + k + 4]));
    }

    // ---- cell ownership: thread owns hcol u, batches {bq, bq+16, bq+32, bq+48} ----
    const int u  = tid & 7;
    const int bq = tid >> 3;                       // 0..15
    const int lane_f = (bq & 7) * 4 + (u & 3);
    const int jreg   = (u >> 2) * 2 + (bq >> 3);

    float c_r[4], h_r[4];
#pragma unroll
    for (int j = 0; j < 4; j++) {
        const int b   = bq + 16 * j;
        const int idx = b * HID + hcbase + u;
        c_r[j] = c0[idx];
        const float h = h0[idx];
        h_r[j] = h;
        g_hbuf[0][((size_t)(j * 128 + cta) * 32 + lane_f) * 4 + jreg] =
            __uint_as_float(f2tf32(h));
    }

    gbar();

    for (int t = 0; t < T_STEPS; t++) {
        const float* hin  = g_hbuf[t & 1];
        float*       hout = g_hbuf[(t + 1) & 1];

        // ---- prefetch x_pre for this step (independent of h; hidden under mma) ----
        float xpv[4][4];
        {
            const float* xp = g_xpre + (size_t)t * BATCH * G4;
#pragma unroll
            for (int j = 0; j < 4; j++) {
                const float* xb = xp + (size_t)(bq + 16 * j) * G4 + hcbase + u;
                xpv[j][0] = __ldg(xb);
                xpv[j][1] = __ldg(xb + HID);
                xpv[j][2] = __ldg(xb + 2 * HID);
                xpv[j][3] = __ldg(xb + 3 * HID);
            }
        }

        float acc[4][4];
#pragma unroll
        for (int n = 0; n < 4; n++)
#pragma unroll
            for (int r = 0; r < 4; r++) acc[n][r] = 0.0f;

        const uint4* Af = (const uint4*)hin + (size_t)(w * 128) * 32 + lane;

        uint4 ab[2][8];
#pragma unroll
        for (int i = 0; i < 8; i++) ab[0][i] = __ldcg(Af + i * 32);

#pragma unroll
        for (int kc = 0; kc < 16; kc++) {
            const int cur = kc & 1;
            if (kc < 15) {
#pragma unroll
                for (int i = 0; i < 8; i++)
                    ab[cur ^ 1][i] = __ldcg(Af + ((kc + 1) * 8 + i) * 32);
            }
#pragma unroll
            for (int i = 0; i < 8; i++) {
                const int ks = kc * 8 + i;
#pragma unroll
                for (int n = 0; n < 4; n++) {
                    const uint2 bv = *(const uint2*)&W_s[((n * 128 + ks) * 32 + lane) * 2];
                    mma_tf32(acc[n], (const uint32_t*)&ab[cur][i], (const uint32_t*)&bv);
                }
            }
        }

        // publish pre to smem
        const int rg = lane >> 2;
        const int cg = 2 * (lane & 3);
#pragma unroll
        for (int n = 0; n < 4; n++) {
            const int colb = n * 8 + cg;
            const int rb   = w * 16 + rg;
            pre_s[rb * 33 + colb]           = acc[n][0];
            pre_s[rb * 33 + colb + 1]       = acc[n][1];
            pre_s[(rb + 8) * 33 + colb]     = acc[n][2];
            pre_s[(rb + 8) * 33 + colb + 1] = acc[n][3];
        }
        __syncthreads();

        // gate math + h/c update + stores
        float* orow = out + (size_t)t * BATCH * HID;
#pragma unroll
        for (int j = 0; j < 4; j++) {
            const int b = bq + 16 * j;
            const float* pb = &pre_s[b * 33];
            const float pi = pb[u]      + xpv[j][0];
            const float pf = pb[8 + u]  + xpv[j][1];
            const float po = pb[16 + u] + xpv[j][2];
            const float pg = pb[24 + u] + xpv[j][3];
            const float ig = 1.0f / (1.0f + __expf(-pi));
            const float fg = 1.0f / (1.0f + __expf(-pf));
            const float og = 1.0f / (1.0f + __expf(-po));
            c_r[j] = fg * c_r[j] + ig * tanhf(pg);
            const float h = og * tanhf(c_r[j]);
            h_r[j] = h;
            orow[b * HID + hcbase + u] = h;
            hout[((size_t)(j * 128 + cta) * 32 + lane_f) * 4 + jreg] =
                __uint_as_float(f2tf32(h));
        }

        gbar();
    }

    // finals: out = [output | h_f | c_f]
    float* hf = out + (size_t)T_STEPS * BATCH * HID;
    float* cf = hf + BATCH * HID;
#pragma unroll
    for (int j = 0; j < 4; j++) {
        const int b = bq + 16 * j;
        hf[b * HID + hcbase + u] = h_r[j];
        cf[b * HID + hcbase + u] = c_r[j];
    }
}

// ---------------- launch ----------------
extern "C" void kernel_launch(void* const* d_in, const int* in_sizes, int n_in,
                              void* d_out, int out_size) {
    const float* input = (const float*)d_in[0];   // [T, B, I]
    const float* h0    = (const float*)d_in[1];   // [1, B, H]
    const float* c0    = (const float*)d_in[2];   // [1, B, H]
    const float* W_ih  = (const float*)d_in[3];   // [4H, I]
    const float* b_ih  = (const float*)d_in[4];   // [4H]
    const float* W_hh  = (const float*)d_in[5];   // [4H, H]
    const float* b_hh  = (const float*)d_in[6];   // [4H]
    float* out = (float*)d_out;

    const int rec_smem = 32768 * 4 + 64 * 33 * 4;  // W_s + pre_s
    cudaFuncSetAttribute(lstm_rec_k, cudaFuncAttributeMaxDynamicSharedMemorySize, rec_smem);

    dim3 g1(G4 / 128, M1 / 128);   // (32, 256)
    gemm1_k<<<g1, 256>>>(input, W_ih, b_ih, b_hh);
    lstm_rec_k<<<NCTA, 128, rec_smem>>>(W_hh, h0, c0, out);
}

// round 5
// speedup vs baseline: 3.3173x; 1.6051x over previous
#include <cuda_runtime.h>
#include <cstdint>
#include <cstddef>

#define T_STEPS 512
#define BATCH   64
#define HID     1024
#define G4      4096
#define M1      (T_STEPS * BATCH)   // 32768
#define NCTA    128

// ---------------- device scratch (no allocs allowed) ----------------
__device__ float    g_xpre[(size_t)M1 * G4];      // 512 MB: [T*B, 4H]
__device__ float    g_hbuf[2][BATCH * HID];       // double-buffered h, A-fragment-major layout
__device__ unsigned g_cnt;                        // zero-init; self-resets each barrier
__device__ unsigned g_gen;                        // zero-init; monotonic across replays

// ---------------- helpers ----------------
__device__ __forceinline__ uint32_t f2tf32(float x) {
    uint32_t r;
    asm("cvt.rna.tf32.f32 %0, %1;" : "=r"(r) : "f"(x));
    return r;
}

__device__ __forceinline__ void mma_tf32(float* c, const uint32_t* a, const uint32_t* b) {
    asm volatile(
        "mma.sync.aligned.m16n8k8.row.col.f32.tf32.tf32.f32 "
        "{%0,%1,%2,%3}, {%4,%5,%6,%7}, {%8,%9}, {%0,%1,%2,%3};"
        : "+f"(c[0]), "+f"(c[1]), "+f"(c[2]), "+f"(c[3])
        : "r"(a[0]), "r"(a[1]), "r"(a[2]), "r"(a[3]), "r"(b[0]), "r"(b[1]));
}

// ---------------- phase 1: x_pre = input @ W_ih^T + b_ih + b_hh (tf32 mma) ----------------
// CTA tile 128x128, 8 warps in 4(M) x 2(N), warp tile 32x64. K-chunk 16, 2-stage pipeline.
__global__ __launch_bounds__(256) void gemm1_k(
    const float* __restrict__ A, const float* __restrict__ W,
    const float* __restrict__ bih, const float* __restrict__ bhh) {
    __shared__ uint32_t As[2][128][20];
    __shared__ uint32_t Bs[2][128][20];

    const int tid   = threadIdx.x;
    const int lane  = tid & 31;
    const int wid   = tid >> 5;
    const int warpM = wid & 3;
    const int warpN = wid >> 2;
    const int m0 = blockIdx.y * 128;
    const int n0 = blockIdx.x * 128;

    const int r1 = tid >> 2;
    const int r2 = r1 + 64;
    const int c4 = (tid & 3) * 4;

    float acc[2][8][4];
#pragma unroll
    for (int mt = 0; mt < 2; mt++)
#pragma unroll
        for (int nt = 0; nt < 8; nt++)
#pragma unroll
            for (int r = 0; r < 4; r++) acc[mt][nt][r] = 0.0f;

    const float* Ap1 = A + (size_t)(m0 + r1) * 1024 + c4;
    const float* Ap2 = A + (size_t)(m0 + r2) * 1024 + c4;
    const float* Wp1 = W + (size_t)(n0 + r1) * 1024 + c4;
    const float* Wp2 = W + (size_t)(n0 + r2) * 1024 + c4;

    const int g  = lane >> 2;
    const int tg = lane & 3;

    float4 ra1, ra2, rb1, rb2;

    ra1 = *(const float4*)(Ap1);
    ra2 = *(const float4*)(Ap2);
    rb1 = *(const float4*)(Wp1);
    rb2 = *(const float4*)(Wp2);
    {
        uint4 u;
        u.x = f2tf32(ra1.x); u.y = f2tf32(ra1.y); u.z = f2tf32(ra1.z); u.w = f2tf32(ra1.w);
        *(uint4*)&As[0][r1][c4] = u;
        u.x = f2tf32(ra2.x); u.y = f2tf32(ra2.y); u.z = f2tf32(ra2.z); u.w = f2tf32(ra2.w);
        *(uint4*)&As[0][r2][c4] = u;
        u.x = f2tf32(rb1.x); u.y = f2tf32(rb1.y); u.z = f2tf32(rb1.z); u.w = f2tf32(rb1.w);
        *(uint4*)&Bs[0][r1][c4] = u;
        u.x = f2tf32(rb2.x); u.y = f2tf32(rb2.y); u.z = f2tf32(rb2.z); u.w = f2tf32(rb2.w);
        *(uint4*)&Bs[0][r2][c4] = u;
    }
    __syncthreads();

    for (int k = 0; k < 64; k++) {
        if (k < 63) {
            const int off = (k + 1) * 16;
            ra1 = *(const float4*)(Ap1 + off);
            ra2 = *(const float4*)(Ap2 + off);
            rb1 = *(const float4*)(Wp1 + off);
            rb2 = *(const float4*)(Wp2 + off);
        }
        const int cur = k & 1;

#pragma unroll
        for (int ksl = 0; ksl < 2; ksl++) {
            const int kb = ksl * 8;
            uint32_t af[2][4];
#pragma unroll
            for (int mt = 0; mt < 2; mt++) {
                const int mb = warpM * 32 + mt * 16;
                af[mt][0] = As[cur][mb + g][kb + tg];
                af[mt][1] = As[cur][mb + 8 + g][kb + tg];
                af[mt][2] = As[cur][mb + g][kb + 4 + tg];
                af[mt][3] = As[cur][mb + 8 + g][kb + 4 + tg];
            }
#pragma unroll
            for (int nt = 0; nt < 8; nt++) {
                const int nb = warpN * 64 + nt * 8;
                uint32_t bf[2];
                bf[0] = Bs[cur][nb + g][kb + tg];
                bf[1] = Bs[cur][nb + g][kb + 4 + tg];
                mma_tf32(acc[0][nt], af[0], bf);
                mma_tf32(acc[1][nt], af[1], bf);
            }
        }
        __syncthreads();
        if (k < 63) {
            const int nxt = cur ^ 1;
            uint4 u;
            u.x = f2tf32(ra1.x); u.y = f2tf32(ra1.y); u.z = f2tf32(ra1.z); u.w = f2tf32(ra1.w);
            *(uint4*)&As[nxt][r1][c4] = u;
            u.x = f2tf32(ra2.x); u.y = f2tf32(ra2.y); u.z = f2tf32(ra2.z); u.w = f2tf32(ra2.w);
            *(uint4*)&As[nxt][r2][c4] = u;
            u.x = f2tf32(rb1.x); u.y = f2tf32(rb1.y); u.z = f2tf32(rb1.z); u.w = f2tf32(rb1.w);
            *(uint4*)&Bs[nxt][r1][c4] = u;
            u.x = f2tf32(rb2.x); u.y = f2tf32(rb2.y); u.z = f2tf32(rb2.z); u.w = f2tf32(rb2.w);
            *(uint4*)&Bs[nxt][r2][c4] = u;
            __syncthreads();
        }
    }

#pragma unroll
    for (int nt = 0; nt < 8; nt++) {
        const int col = n0 + warpN * 64 + nt * 8 + 2 * tg;
        const float bias0 = bih[col] + bhh[col];
        const float bias1 = bih[col + 1] + bhh[col + 1];
#pragma unroll
        for (int mt = 0; mt < 2; mt++) {
            const int row = m0 + warpM * 32 + mt * 16 + g;
            float2 v0; v0.x = acc[mt][nt][0] + bias0; v0.y = acc[mt][nt][1] + bias1;
            *(float2*)&g_xpre[(size_t)row * G4 + col] = v0;
            float2 v1; v1.x = acc[mt][nt][2] + bias0; v1.y = acc[mt][nt][3] + bias1;
            *(float2*)&g_xpre[(size_t)(row + 8) * G4 + col] = v1;
        }
    }
}

// ---------------- grid-wide barrier: self-resetting, replay-safe ----------------
__device__ __forceinline__ void gbar() {
    __syncthreads();
    if (threadIdx.x == 0) {
        volatile unsigned* vgen = &g_gen;
        const unsigned gen0 = *vgen;
        __threadfence();
        if (atomicAdd(&g_cnt, 1u) == NCTA - 1u) {
            g_cnt = 0u;
            __threadfence();
            *vgen = gen0 + 1u;
        } else {
            while (*vgen == gen0) { __nanosleep(32); }
        }
    }
    __syncthreads();
}

// ---------------- phase 2: persistent recurrence (tf32 mma, K-split x2) ----------------
// 128 CTAs x 256 threads (8 warps). CTA owns 32 gate-cols: {g*1024 + cta*8 + u}.
// Warp w: mt = w&3 (16-batch tile), kh = w>>2 (K half). Partials summed in gate phase.
__global__ __launch_bounds__(256) void lstm_rec_k(
    const float* __restrict__ Whh, const float* __restrict__ h0,
    const float* __restrict__ c0, float* __restrict__ out) {
    extern __shared__ uint32_t smem[];
    uint32_t* W_s   = smem;                        // 4*128*32*2 words (128 KB)
    float*    pre_s = (float*)(smem + 32768);      // 2 x [64][33]

    const int tid    = threadIdx.x;
    const int lane   = tid & 31;
    const int w      = tid >> 5;                   // 0..7
    const int mt     = w & 3;                      // batch tile
    const int kh     = w >> 2;                     // K half
    const int cta    = blockIdx.x;
    const int hcbase = cta * 8;

    // ---- fill W fragments (one-time) ----
    for (int idx = tid; idx < 16384; idx += 256) {
        const int li = idx & 31;
        const int ks = (idx >> 5) & 127;
        const int n  = idx >> 12;
        const size_t row = (size_t)(n * HID + hcbase + (li >> 2)) * HID;
        const int k = ks * 8 + (li & 3);
        W_s[idx * 2]     = f2tf32(__ldg(&Whh[row + k]));
        W_s[idx * 2 + 1] = f2tf32(__ldg(&Whh[row + k + 4]));
    }

    // ---- cell ownership: thread owns hcol u, batches {bq2, bq2+32} ----
    const int u   = tid & 7;
    const int bq2 = tid >> 3;                      // 0..31
    const int lane_f = (bq2 & 7) * 4 + (u & 3);
    const int jreg   = ((u >> 2) & 1) * 2 + ((bq2 >> 3) & 1);
    const int mtb0   = bq2 >> 4;                   // 0..1; second cell uses mtb0+2

    float c_r[2], h_r[2];
#pragma unroll
    for (int j = 0; j < 2; j++) {
        const int b   = bq2 + 32 * j;
        const int idx = b * HID + hcbase + u;
        c_r[j] = c0[idx];
        const float h = h0[idx];
        h_r[j] = h;
        g_hbuf[0][((size_t)((mtb0 + 2 * j) * 128 + cta) * 32 + lane_f) * 4 + jreg] =
            __uint_as_float(f2tf32(h));
    }

    gbar();

    for (int t = 0; t < T_STEPS; t++) {
        const float* hin  = g_hbuf[t & 1];
        float*       hout = g_hbuf[(t + 1) & 1];

        // ---- prefetch x_pre for this step (independent of h) ----
        float xpv[2][4];
        {
            const float* xp = g_xpre + (size_t)t * BATCH * G4;
#pragma unroll
            for (int j = 0; j < 2; j++) {
                const float* xb = xp + (size_t)(bq2 + 32 * j) * G4 + hcbase + u;
                xpv[j][0] = __ldg(xb);
                xpv[j][1] = __ldg(xb + HID);
                xpv[j][2] = __ldg(xb + 2 * HID);
                xpv[j][3] = __ldg(xb + 3 * HID);
            }
        }

        float acc[4][4];
#pragma unroll
        for (int n = 0; n < 4; n++)
#pragma unroll
            for (int r = 0; r < 4; r++) acc[n][r] = 0.0f;

        // warp reads 64 ks-blocks: [kh*64, kh*64+64)
        const uint4* Af = (const uint4*)hin + (size_t)(mt * 128 + kh * 64) * 32 + lane;

        uint4 ab[2][8];
#pragma unroll
        for (int i = 0; i < 8; i++) ab[0][i] = __ldcg(Af + i * 32);

#pragma unroll
        for (int kc = 0; kc < 8; kc++) {
            const int cur = kc & 1;
            if (kc < 7) {
#pragma unroll
                for (int i = 0; i < 8; i++)
                    ab[cur ^ 1][i] = __ldcg(Af + ((kc + 1) * 8 + i) * 32);
            }
#pragma unroll
            for (int i = 0; i < 8; i++) {
                const int ksg = kh * 64 + kc * 8 + i;
#pragma unroll
                for (int n = 0; n < 4; n++) {
                    const uint2 bv = *(const uint2*)&W_s[((n * 128 + ksg) * 32 + lane) * 2];
                    mma_tf32(acc[n], (const uint32_t*)&ab[cur][i], (const uint32_t*)&bv);
                }
            }
        }

        // publish partials to this K-half's buffer
        {
            float* pb = pre_s + kh * 2112;         // 64*33
            const int rg = lane >> 2;
            const int cg = 2 * (lane & 3);
#pragma unroll
            for (int n = 0; n < 4; n++) {
                const int colb = n * 8 + cg;
                const int rb   = mt * 16 + rg;
                pb[rb * 33 + colb]           = acc[n][0];
                pb[rb * 33 + colb + 1]       = acc[n][1];
                pb[(rb + 8) * 33 + colb]     = acc[n][2];
                pb[(rb + 8) * 33 + colb + 1] = acc[n][3];
            }
        }
        __syncthreads();

        // gate math + h/c update + stores (2 cells per thread)
        float* orow = out + (size_t)t * BATCH * HID;
#pragma unroll
        for (int j = 0; j < 2; j++) {
            const int b = bq2 + 32 * j;
            const float* p0 = &pre_s[b * 33];
            const float* p1 = p0 + 2112;
            const float pi = p0[u]      + p1[u]      + xpv[j][0];
            const float pf = p0[8 + u]  + p1[8 + u]  + xpv[j][1];
            const float po = p0[16 + u] + p1[16 + u] + xpv[j][2];
            const float pg = p0[24 + u] + p1[24 + u] + xpv[j][3];
            const float ig = 1.0f / (1.0f + __expf(-pi));
            const float fg = 1.0f / (1.0f + __expf(-pf));
            const float og = 1.0f / (1.0f + __expf(-po));
            c_r[j] = fg * c_r[j] + ig * tanhf(pg);
            const float h = og * tanhf(c_r[j]);
            h_r[j] = h;
            orow[b * HID + hcbase + u] = h;
            hout[((size_t)((mtb0 + 2 * j) * 128 + cta) * 32 + lane_f) * 4 + jreg] =
                __uint_as_float(f2tf32(h));
        }

        gbar();
    }

    // finals: out = [output | h_f | c_f]
    float* hf = out + (size_t)T_STEPS * BATCH * HID;
    float* cf = hf + BATCH * HID;
#pragma unroll
    for (int j = 0; j < 2; j++) {
        const int b = bq2 + 32 * j;
        hf[b * HID + hcbase + u] = h_r[j];
        cf[b * HID + hcbase + u] = c_r[j];
    }
}

// ---------------- launch ----------------
extern "C" void kernel_launch(void* const* d_in, const int* in_sizes, int n_in,
                              void* d_out, int out_size) {
    const float* input = (const float*)d_in[0];   // [T, B, I]
    const float* h0    = (const float*)d_in[1];   // [1, B, H]
    const float* c0    = (const float*)d_in[2];   // [1, B, H]
    const float* W_ih  = (const float*)d_in[3];   // [4H, I]
    const float* b_ih  = (const float*)d_in[4];   // [4H]
    const float* W_hh  = (const float*)d_in[5];   // [4H, H]
    const float* b_hh  = (const float*)d_in[6];   // [4H]
    float* out = (float*)d_out;

    const int rec_smem = 32768 * 4 + 2 * 64 * 33 * 4;  // W_s + 2x pre_s = 147968
    cudaFuncSetAttribute(lstm_rec_k, cudaFuncAttributeMaxDynamicSharedMemorySize, rec_smem);

    dim3 g1(G4 / 128, M1 / 128);   // (32, 256)
    gemm1_k<<<g1, 256>>>(input, W_ih, b_ih, b_hh);
    lstm_rec_k<<<NCTA, 256, rec_smem>>>(W_hh, h0, c0, out);
}

// round 6
// speedup vs baseline: 3.7817x; 1.1400x over previous
#include <cuda_runtime.h>
#include <cstdint>
#include <cstddef>

#define T_STEPS 512
#define BATCH   64
#define HID     1024
#define G4      4096
#define M1      (T_STEPS * BATCH)   // 32768
#define NCTA    128

// ---------------- device scratch (no allocs allowed) ----------------
__device__ float    g_xpre[(size_t)M1 * G4];      // 512 MB: [T*B, 4H]
__device__ float    g_hbuf[2][BATCH * HID];       // double-buffered h, A-fragment-major layout
__device__ unsigned g_cnt1[16];                   // tree barrier: 16 groups of 8 CTAs
__device__ unsigned g_cnt2;                       // tree barrier: root (16 leaders)
__device__ unsigned g_gen;                        // monotonic generation

// ---------------- helpers ----------------
__device__ __forceinline__ uint32_t f2tf32(float x) {
    uint32_t r;
    asm("cvt.rna.tf32.f32 %0, %1;" : "=r"(r) : "f"(x));
    return r;
}

__device__ __forceinline__ void mma_tf32(float* c, const uint32_t* a, const uint32_t* b) {
    asm volatile(
        "mma.sync.aligned.m16n8k8.row.col.f32.tf32.tf32.f32 "
        "{%0,%1,%2,%3}, {%4,%5,%6,%7}, {%8,%9}, {%0,%1,%2,%3};"
        : "+f"(c[0]), "+f"(c[1]), "+f"(c[2]), "+f"(c[3])
        : "r"(a[0]), "r"(a[1]), "r"(a[2]), "r"(a[3]), "r"(b[0]), "r"(b[1]));
}

__device__ __forceinline__ void cp_async16(uint32_t saddr, const void* gaddr) {
    asm volatile("cp.async.cg.shared.global [%0], [%1], 16;\n"
                 :: "r"(saddr), "l"(gaddr));
}
#define CP_COMMIT() asm volatile("cp.async.commit_group;\n" ::: "memory")
#define CP_WAIT1()  asm volatile("cp.async.wait_group 1;\n" ::: "memory")

// ---------------- phase 1: x_pre = input @ W_ih^T + b_ih + b_hh (tf32 mma) ----------------
// CTA tile 128x128, 8 warps in 4(M) x 2(N), warp tile 32x64. K-chunk 16, 2-stage pipeline.
__global__ __launch_bounds__(256) void gemm1_k(
    const float* __restrict__ A, const float* __restrict__ W,
    const float* __restrict__ bih, const float* __restrict__ bhh) {
    __shared__ uint32_t As[2][128][20];
    __shared__ uint32_t Bs[2][128][20];

    const int tid   = threadIdx.x;
    const int lane  = tid & 31;
    const int wid   = tid >> 5;
    const int warpM = wid & 3;
    const int warpN = wid >> 2;
    const int m0 = blockIdx.y * 128;
    const int n0 = blockIdx.x * 128;

    const int r1 = tid >> 2;
    const int r2 = r1 + 64;
    const int c4 = (tid & 3) * 4;

    float acc[2][8][4];
#pragma unroll
    for (int mt = 0; mt < 2; mt++)
#pragma unroll
        for (int nt = 0; nt < 8; nt++)
#pragma unroll
            for (int r = 0; r < 4; r++) acc[mt][nt][r] = 0.0f;

    const float* Ap1 = A + (size_t)(m0 + r1) * 1024 + c4;
    const float* Ap2 = A + (size_t)(m0 + r2) * 1024 + c4;
    const float* Wp1 = W + (size_t)(n0 + r1) * 1024 + c4;
    const float* Wp2 = W + (size_t)(n0 + r2) * 1024 + c4;

    const int g  = lane >> 2;
    const int tg = lane & 3;

    float4 ra1, ra2, rb1, rb2;

    ra1 = *(const float4*)(Ap1);
    ra2 = *(const float4*)(Ap2);
    rb1 = *(const float4*)(Wp1);
    rb2 = *(const float4*)(Wp2);
    {
        uint4 u;
        u.x = f2tf32(ra1.x); u.y = f2tf32(ra1.y); u.z = f2tf32(ra1.z); u.w = f2tf32(ra1.w);
        *(uint4*)&As[0][r1][c4] = u;
        u.x = f2tf32(ra2.x); u.y = f2tf32(ra2.y); u.z = f2tf32(ra2.z); u.w = f2tf32(ra2.w);
        *(uint4*)&As[0][r2][c4] = u;
        u.x = f2tf32(rb1.x); u.y = f2tf32(rb1.y); u.z = f2tf32(rb1.z); u.w = f2tf32(rb1.w);
        *(uint4*)&Bs[0][r1][c4] = u;
        u.x = f2tf32(rb2.x); u.y = f2tf32(rb2.y); u.z = f2tf32(rb2.z); u.w = f2tf32(rb2.w);
        *(uint4*)&Bs[0][r2][c4] = u;
    }
    __syncthreads();

    for (int k = 0; k < 64; k++) {
        if (k < 63) {
            const int off = (k + 1) * 16;
            ra1 = *(const float4*)(Ap1 + off);
            ra2 = *(const float4*)(Ap2 + off);
            rb1 = *(const float4*)(Wp1 + off);
            rb2 = *(const float4*)(Wp2 + off);
        }
        const int cur = k & 1;

#pragma unroll
        for (int ksl = 0; ksl < 2; ksl++) {
            const int kb = ksl * 8;
            uint32_t af[2][4];
#pragma unroll
            for (int mt = 0; mt < 2; mt++) {
                const int mb = warpM * 32 + mt * 16;
                af[mt][0] = As[cur][mb + g][kb + tg];
                af[mt][1] = As[cur][mb + 8 + g][kb + tg];
                af[mt][2] = As[cur][mb + g][kb + 4 + tg];
                af[mt][3] = As[cur][mb + 8 + g][kb + 4 + tg];
            }
#pragma unroll
            for (int nt = 0; nt < 8; nt++) {
                const int nb = warpN * 64 + nt * 8;
                uint32_t bf[2];
                bf[0] = Bs[cur][nb + g][kb + tg];
                bf[1] = Bs[cur][nb + g][kb + 4 + tg];
                mma_tf32(acc[0][nt], af[0], bf);
                mma_tf32(acc[1][nt], af[1], bf);
            }
        }
        __syncthreads();
        if (k < 63) {
            const int nxt = cur ^ 1;
            uint4 u;
            u.x = f2tf32(ra1.x); u.y = f2tf32(ra1.y); u.z = f2tf32(ra1.z); u.w = f2tf32(ra1.w);
            *(uint4*)&As[nxt][r1][c4] = u;
            u.x = f2tf32(ra2.x); u.y = f2tf32(ra2.y); u.z = f2tf32(ra2.z); u.w = f2tf32(ra2.w);
            *(uint4*)&As[nxt][r2][c4] = u;
            u.x = f2tf32(rb1.x); u.y = f2tf32(rb1.y); u.z = f2tf32(rb1.z); u.w = f2tf32(rb1.w);
            *(uint4*)&Bs[nxt][r1][c4] = u;
            u.x = f2tf32(rb2.x); u.y = f2tf32(rb2.y); u.z = f2tf32(rb2.z); u.w = f2tf32(rb2.w);
            *(uint4*)&Bs[nxt][r2][c4] = u;
            __syncthreads();
        }
    }

#pragma unroll
    for (int nt = 0; nt < 8; nt++) {
        const int col = n0 + warpN * 64 + nt * 8 + 2 * tg;
        const float bias0 = bih[col] + bhh[col];
        const float bias1 = bih[col + 1] + bhh[col + 1];
#pragma unroll
        for (int mt = 0; mt < 2; mt++) {
            const int row = m0 + warpM * 32 + mt * 16 + g;
            float2 v0; v0.x = acc[mt][nt][0] + bias0; v0.y = acc[mt][nt][1] + bias1;
            *(float2*)&g_xpre[(size_t)row * G4 + col] = v0;
            float2 v1; v1.x = acc[mt][nt][2] + bias0; v1.y = acc[mt][nt][3] + bias1;
            *(float2*)&g_xpre[(size_t)(row + 8) * G4 + col] = v1;
        }
    }
}

// ---------------- grid-wide barrier: two-level tree, self-resetting ----------------
__device__ __forceinline__ void gbar(int cta) {
    __syncthreads();
    if (threadIdx.x == 0) {
        volatile unsigned* vgen = &g_gen;
        const unsigned gen0 = *vgen;      // stable until all arrive
        __threadfence();                   // publish h/c stores before arrival
        const int grp = cta >> 3;
        if (atomicAdd(&g_cnt1[grp], 1u) == 7u) {
            g_cnt1[grp] = 0u;              // safe: group fully arrived, none re-enter yet
            __threadfence();
            if (atomicAdd(&g_cnt2, 1u) == 15u) {
                g_cnt2 = 0u;
                __threadfence();
                *vgen = gen0 + 1u;         // release
            } else {
                while (*vgen == gen0) { __nanosleep(16); }
            }
        } else {
            while (*vgen == gen0) { __nanosleep(16); }
        }
    }
    __syncthreads();
}

// ---------------- phase 2: persistent recurrence (tf32 mma, K-split x2, cp.async h) ----------------
// 128 CTAs x 256 threads (8 warps). Warp w: mt = w&3 (16-batch tile), kh = w>>2 (K half).
// h chunks staged via cp.async into warp-private smem double buffers (no reg pressure,
// true latency overlap). Partials summed in gate phase.
__global__ __launch_bounds__(256) void lstm_rec_k(
    const float* __restrict__ Whh, const float* __restrict__ h0,
    const float* __restrict__ c0, float* __restrict__ out) {
    extern __shared__ uint32_t smem[];
    uint32_t* W_s   = smem;                          // 32768 u32 (128 KB)
    float*    pre_s = (float*)(smem + 32768);        // 2 x [64][33]  (4224 floats)
    uint32_t* hs    = smem + 32768 + 4224;           // 16384 u32 (64 KB): 8 warps x 2 x 4KB

    const int tid    = threadIdx.x;
    const int lane   = tid & 31;
    const int w      = tid >> 5;                     // 0..7
    const int mt     = w & 3;                        // batch tile
    const int kh     = w >> 2;                       // K half
    const int cta    = blockIdx.x;
    const int hcbase = cta * 8;

    // warp-private h staging base (byte address in shared space), lane offset folded in
    const uint32_t hs_w = (uint32_t)__cvta_generic_to_shared(hs) + w * 8192 + lane * 16;

    // ---- fill W fragments (one-time) ----
    for (int idx = tid; idx < 16384; idx += 256) {
        const int li = idx & 31;
        const int ks = (idx >> 5) & 127;
        const int n  = idx >> 12;
        const size_t row = (size_t)(n * HID + hcbase + (li >> 2)) * HID;
        const int k = ks * 8 + (li & 3);
        W_s[idx * 2]     = f2tf32(__ldg(&Whh[row + k]));
        W_s[idx * 2 + 1] = f2tf32(__ldg(&Whh[row + k + 4]));
    }

    // ---- cell ownership: thread owns hcol u, batches {bq2, bq2+32} ----
    const int u   = tid & 7;
    const int bq2 = tid >> 3;                        // 0..31
    const int lane_f = (bq2 & 7) * 4 + (u & 3);
    const int jreg   = ((u >> 2) & 1) * 2 + ((bq2 >> 3) & 1);
    const int mtb0   = bq2 >> 4;                     // 0..1; second cell uses mtb0+2

    float c_r[2], h_r[2];
#pragma unroll
    for (int j = 0; j < 2; j++) {
        const int b   = bq2 + 32 * j;
        const int idx = b * HID + hcbase + u;
        c_r[j] = c0[idx];
        const float h = h0[idx];
        h_r[j] = h;
        g_hbuf[0][((size_t)((mtb0 + 2 * j) * 128 + cta) * 32 + lane_f) * 4 + jreg] =
            __uint_as_float(f2tf32(h));
    }

    gbar(cta);

    for (int t = 0; t < T_STEPS; t++) {
        const float* hin  = g_hbuf[t & 1];
        float*       hout = g_hbuf[(t + 1) & 1];

        // ---- prefetch x_pre for this step (independent of h; hidden under mma) ----
        float xpv[2][4];
        {
            const float* xp = g_xpre + (size_t)t * BATCH * G4;
#pragma unroll
            for (int j = 0; j < 2; j++) {
                const float* xb = xp + (size_t)(bq2 + 32 * j) * G4 + hcbase + u;
                xpv[j][0] = __ldg(xb);
                xpv[j][1] = __ldg(xb + HID);
                xpv[j][2] = __ldg(xb + 2 * HID);
                xpv[j][3] = __ldg(xb + 3 * HID);
            }
        }

        float acc[4][4];
#pragma unroll
        for (int n = 0; n < 4; n++)
#pragma unroll
            for (int r = 0; r < 4; r++) acc[n][r] = 0.0f;

        // warp's h region: 64 ks-blocks [kh*64, kh*64+64), 8 chunks of 4 KB (contiguous)
        const char* hsrc = (const char*)hin + (size_t)(mt * 128 + kh * 64) * 512 + lane * 16;

        // prologue: stage chunk 0
#pragma unroll
        for (int i = 0; i < 8; i++) cp_async16(hs_w + i * 512, hsrc + i * 512);
        CP_COMMIT();

#pragma unroll
        for (int kc = 0; kc < 8; kc++) {
            // stage chunk kc+1 while computing kc
            if (kc < 7) {
                const char*    src = hsrc + (kc + 1) * 4096;
                const uint32_t dst = hs_w + ((kc + 1) & 1) * 4096;
#pragma unroll
                for (int i = 0; i < 8; i++) cp_async16(dst + i * 512, src + i * 512);
            }
            CP_COMMIT();
            CP_WAIT1();               // chunk kc resident
            __syncwarp();

            const uint32_t cur = hs_w + (kc & 1) * 4096;
#pragma unroll
            for (int i = 0; i < 8; i++) {
                uint32_t a0, a1, a2, a3;
                asm volatile("ld.shared.v4.b32 {%0,%1,%2,%3}, [%4];"
                             : "=r"(a0), "=r"(a1), "=r"(a2), "=r"(a3)
                             : "r"(cur + i * 512));
                uint32_t af[4] = {a0, a1, a2, a3};
                const int ksg = kh * 64 + kc * 8 + i;
#pragma unroll
                for (int n = 0; n < 4; n++) {
                    const uint2 bv = *(const uint2*)&W_s[((n * 128 + ksg) * 32 + lane) * 2];
                    mma_tf32(acc[n], af, (const uint32_t*)&bv);
                }
            }
        }

        // publish partials to this K-half's buffer
        {
            float* pb = pre_s + kh * 2112;           // 64*33
            const int rg = lane >> 2;
            const int cg = 2 * (lane & 3);
#pragma unroll
            for (int n = 0; n < 4; n++) {
                const int colb = n * 8 + cg;
                const int rb   = mt * 16 + rg;
                pb[rb * 33 + colb]           = acc[n][0];
                pb[rb * 33 + colb + 1]       = acc[n][1];
                pb[(rb + 8) * 33 + colb]     = acc[n][2];
                pb[(rb + 8) * 33 + colb + 1] = acc[n][3];
            }
        }
        __syncthreads();

        // gate math + h/c update + stores (2 cells per thread)
        float* orow = out + (size_t)t * BATCH * HID;
#pragma unroll
        for (int j = 0; j < 2; j++) {
            const int b = bq2 + 32 * j;
            const float* p0 = &pre_s[b * 33];
            const float* p1 = p0 + 2112;
            const float pi = p0[u]      + p1[u]      + xpv[j][0];
            const float pf = p0[8 + u]  + p1[8 + u]  + xpv[j][1];
            const float po = p0[16 + u] + p1[16 + u] + xpv[j][2];
            const float pg = p0[24 + u] + p1[24 + u] + xpv[j][3];
            const float ig = 1.0f / (1.0f + __expf(-pi));
            const float fg = 1.0f / (1.0f + __expf(-pf));
            const float og = 1.0f / (1.0f + __expf(-po));
            c_r[j] = fg * c_r[j] + ig * tanhf(pg);
            const float h = og * tanhf(c_r[j]);
            h_r[j] = h;
            hout[((size_t)((mtb0 + 2 * j) * 128 + cta) * 32 + lane_f) * 4 + jreg] =
                __uint_as_float(f2tf32(h));
            orow[b * HID + hcbase + u] = h;
        }

        gbar(cta);
    }

    // finals: out = [output | h_f | c_f]
    float* hf = out + (size_t)T_STEPS * BATCH * HID;
    float* cf = hf + BATCH * HID;
#pragma unroll
    for (int j = 0; j < 2; j++) {
        const int b = bq2 + 32 * j;
        hf[b * HID + hcbase + u] = h_r[j];
        cf[b * HID + hcbase + u] = c_r[j];
    }
}

// ---------------- launch ----------------
extern "C" void kernel_launch(void* const* d_in, const int* in_sizes, int n_in,
                              void* d_out, int out_size) {
    const float* input = (const float*)d_in[0];   // [T, B, I]
    const float* h0    = (const float*)d_in[1];   // [1, B, H]
    const float* c0    = (const float*)d_in[2];   // [1, B, H]
    const float* W_ih  = (const float*)d_in[3];   // [4H, I]
    const float* b_ih  = (const float*)d_in[4];   // [4H]
    const float* W_hh  = (const float*)d_in[5];   // [4H, H]
    const float* b_hh  = (const float*)d_in[6];   // [4H]
    float* out = (float*)d_out;

    // W_s (131072 B) + pre_s (16896 B) + h staging (65536 B) = 213504 B
    const int rec_smem = (32768 + 4224 + 16384) * 4;
    cudaFuncSetAttribute(lstm_rec_k, cudaFuncAttributeMaxDynamicSharedMemorySize, rec_smem);

    dim3 g1(G4 / 128, M1 / 128);   // (32, 256)
    gemm1_k<<<g1, 256>>>(input, W_ih, b_ih, b_hh);
    lstm_rec_k<<<NCTA, 256, rec_smem>>>(W_hh, h0, c0, out);
}